// round 12
// baseline (speedup 1.0000x reference)
#include <cuda_runtime.h>
#include <cuda_bf16.h>
#include <cstdint>

// ---------------------------------------------------------------------------
// MemristiveLinear == y = x @ w + b (512^3 fp32), tcgen05 bf16 split:
//   x = xh+xl, w = wh+wl;  y ~= xh@wh + xh@wl + xl@wh  (+b)
//
// R12: R11 with the split-K join de-fattened:
//   - fence-promotion join: __syncthreads + tid0-only fence.acq_rel.gpu
//     around the tile atomic (was: 2x per-thread __threadfence = ~1024
//     MEMBAR.GPU per CTA)
//   - winner CTA keeps its own partial in registers: y = regs + peer + bias
//     (skips 16KB own-partial re-read; final phase runs on 128 threads)
//   - bias prefetched into smem at kernel start
// Everything else identical to R11 (single launch, 128 CTAs, in-kernel
// convert, 48 MMA dispatches, idesc/layout validated R5-R11).
// ---------------------------------------------------------------------------

#if defined(__CUDA_ARCH_FEAT_SM103_ALL) || defined(__CUDA_ARCH_FEAT_SM100_ALL) || \
    defined(__CUDA_ARCH_FEAT_SM101_ALL) || defined(__CUDA_ARCH_SPECIFIC__) ||     \
    defined(__CUDA_ARCH_FAMILY_SPECIFIC__)
#define TC_OK 1
#else
#define TC_OK 0
#endif

#define MD 512
#define ND 512
#define KD 512
#define KH 256                       // K per split-K half

__device__ float gPart[2][MD * ND];  // split-K partials (2 MB)
__device__ int gCnt[64];             // per-tile semaphores (zero-init)

#define SWZ(o) ((o) ^ (((o) >> 3) & 0x70))
#define DESC_BASE 0x4000404000010000ull
#define MK_DESC(addr) (DESC_BASE | (((unsigned long long)((addr) >> 4)) & 0x3FFF))
// kind::f16 idesc: F32 acc, BF16 a/b, M=128, N=32 (validated R5-R11)
#define IDESC ((1u << 4) | (1u << 7) | (1u << 10) | (4u << 17) | (8u << 24))

// smem map (relative to 1024-aligned base):
//   0: tmem ptr | 8: mbar | 64: win flag | 128: bias[32]
//   Ah @ 1024 (64K) | Al @ 66560 (64K) | Wh @ 132096 (16K) | Wl @ 148480 (16K)
#define OFF_AH 1024
#define OFF_AL 66560
#define OFF_WH 132096
#define OFF_WL 148480
#define SMEM_DYN 166912

__device__ __forceinline__ uint32_t s2u(const void* p) {
    uint32_t a;
    asm("{ .reg .u64 t; cvta.to.shared.u64 t, %1; cvt.u32.u64 %0, t; }"
        : "=r"(a) : "l"(p));
    return a;
}

// Split two fp32 into packed bf16x2 hi + lo (a in low half). Validated R6-R11.
__device__ __forceinline__ void split2(float a, float b, unsigned& h,
                                       unsigned& l) {
    unsigned hp;
    asm("cvt.rn.bf16x2.f32 %0, %1, %2;" : "=r"(hp) : "f"(b), "f"(a));
    float fa = __uint_as_float(hp << 16);
    float fb = __uint_as_float(hp & 0xffff0000u);
    float ra = a - fa;
    float rb = b - fb;
    asm("cvt.rn.bf16x2.f32 %0, %1, %2;" : "=r"(l) : "f"(rb), "f"(ra));
    h = hp;
}

#if TC_OK
__device__ __forceinline__ void mma_f16_ss(uint32_t d, unsigned long long ad,
                                           unsigned long long bd,
                                           uint32_t idesc, uint32_t en) {
    asm volatile(
        "{\n\t.reg .pred p;\n\tsetp.ne.u32 p, %5, 0;\n\t"
        "tcgen05.mma.cta_group::1.kind::f16 [%0], %1, %2, %3, {%4, %4, %4, %4}, p;\n\t}"
        :: "r"(d), "l"(ad), "l"(bd), "r"(idesc), "r"(0u), "r"(en)
        : "memory");
}

#define MBAR_INIT(a) \
    asm volatile("mbarrier.init.shared.b64 [%0], %1;" :: "r"(a), "r"(1u) : "memory")

#define MBAR_WAITP(a, ph) do {                                                \
    unsigned _m = (a), _p = (ph), _d;                                         \
    asm volatile("{\n\t.reg .pred p;\n\t"                                     \
        "mbarrier.try_wait.parity.acquire.cta.shared::cta.b64 p, [%1], %2;\n\t" \
        "selp.b32 %0, 1, 0, p;\n\t}" : "=r"(_d) : "r"(_m), "r"(_p) : "memory"); \
    if (!_d) {                                                                \
        asm volatile("{\n\t.reg .pred P1;\n\t"                                \
            "WL_%=:\n\t"                                                      \
            "mbarrier.try_wait.parity.acquire.cta.shared::cta.b64 P1, [%0], %1, 0x989680;\n\t" \
            "@P1 bra.uni WD_%=;\n\t"                                          \
            "bra.uni WL_%=;\n\t"                                              \
            "WD_%=:\n\t}" :: "r"(_m), "r"(_p) : "memory");                    \
    }                                                                         \
} while (0)

#define TC_COMMIT(a) \
    asm volatile("tcgen05.commit.cta_group::1.mbarrier::arrive::one.shared::cluster.b64 [%0];" \
                 :: "r"(a) : "memory")

#define LDTM_X32(r, addr)                                                     \
    asm volatile("tcgen05.ld.sync.aligned.32x32b.x32.b32 "                    \
        "{%0, %1, %2, %3, %4, %5, %6, %7, "                                   \
        " %8, %9, %10, %11, %12, %13, %14, %15, "                             \
        " %16, %17, %18, %19, %20, %21, %22, %23, "                           \
        " %24, %25, %26, %27, %28, %29, %30, %31}, [%32];"                    \
        : "=r"((r)[0]),  "=r"((r)[1]),  "=r"((r)[2]),  "=r"((r)[3]),          \
          "=r"((r)[4]),  "=r"((r)[5]),  "=r"((r)[6]),  "=r"((r)[7]),          \
          "=r"((r)[8]),  "=r"((r)[9]),  "=r"((r)[10]), "=r"((r)[11]),         \
          "=r"((r)[12]), "=r"((r)[13]), "=r"((r)[14]), "=r"((r)[15]),         \
          "=r"((r)[16]), "=r"((r)[17]), "=r"((r)[18]), "=r"((r)[19]),         \
          "=r"((r)[20]), "=r"((r)[21]), "=r"((r)[22]), "=r"((r)[23]),         \
          "=r"((r)[24]), "=r"((r)[25]), "=r"((r)[26]), "=r"((r)[27]),         \
          "=r"((r)[28]), "=r"((r)[29]), "=r"((r)[30]), "=r"((r)[31])          \
        : "r"(addr))
#endif  // TC_OK

__global__ __launch_bounds__(512, 1)
void fused_kernel(const float* __restrict__ X, const float* __restrict__ W,
                  const float* __restrict__ Bias, float* __restrict__ Y) {
    extern __shared__ char dsm[];
    const int tid = threadIdx.x;
    const int n0 = blockIdx.x * 32;
    const int m0 = blockIdx.y * 128;
    const int kz = blockIdx.z;            // split-K half 0/1
    const int tile = blockIdx.y * 16 + blockIdx.x;

#if TC_OK
    const uint32_t raw = s2u(dsm);
    const uint32_t base = (raw + 1023u) & ~1023u;
    char* dbase = dsm + (base - raw);

    const int wid = tid >> 5;
    const int lid = tid & 31;

    // Prefetch bias into smem (hides its cold-load latency under everything).
    if (tid < 8)
        *(float4*)(dbase + 128 + 16 * tid) = ((const float4*)(Bias + n0))[tid];

    if (wid == 0)
        asm volatile(
            "tcgen05.alloc.cta_group::1.sync.aligned.shared::cta.b32 [%0], %1;"
            :: "r"(base), "r"(64u) : "memory");
    if (tid == 0) MBAR_INIT(base + 8);

    // ---- convert A slice: 128 m x 256 k fp32 -> bf16 hi/lo (blocked atom)
    {
        const int arow0 = tid >> 6;          // 0..7
        const int akq = tid & 63;            // float4 index in row
        const int aac = akq >> 4;            // atom col (0..3)
        const int aicb = ((4 * akq) & 63) * 2;  // byte off within atom row
        const float* xb = X + kz * KH + 4 * akq;
#pragma unroll
        for (int j = 0; j < 16; j++) {
            const int row = j * 8 + arow0;
            float4 v = *(const float4*)(xb + (size_t)(m0 + row) * KD);
            unsigned h01, l01, h23, l23;
            split2(v.x, v.y, h01, l01);
            split2(v.z, v.w, h23, l23);
            const int off = SWZ(((row >> 3) + aac * 16) * 1024 +
                                (row & 7) * 128 + aicb);
            *(uint2*)(dbase + OFF_AH + off) = make_uint2(h01, h23);
            *(uint2*)(dbase + OFF_AL + off) = make_uint2(l01, l23);
        }
    }
    // ---- convert W slice: 32 n x 256 k (coalesced: lane = n column) ------
    {
        const int wn = tid & 31;
        const int wk0 = 2 * (tid >> 5);      // even k base (0..30)
        const float* wb = W + (size_t)(kz * KH) * ND + n0 + wn;
        const int nbase = ((wn >> 3)) * 1024 + (wn & 7) * 128;
#pragma unroll
        for (int p = 0; p < 8; p++) {
            const int k = wk0 + 32 * p;
            float w0 = wb[(size_t)k * ND];
            float w1 = wb[(size_t)(k + 1) * ND];
            unsigned h, l;
            split2(w0, w1, h, l);
            const int off = SWZ(nbase + (k >> 6) * 4096 + (k & 63) * 2);
            *(unsigned*)(dbase + OFF_WH + off) = h;
            *(unsigned*)(dbase + OFF_WL + off) = l;
        }
    }

    // BAR drains all pending STS; single-thread proxy fence then publishes
    // generic->async cheaply (test_tma_store.cu pattern).
    __syncthreads();
    uint32_t tmem;
    asm("ld.shared.b32 %0, [%1];" : "=r"(tmem) : "r"(base));

    if (tid == 0) {
        asm volatile("fence.proxy.async.shared::cta;" ::: "memory");
        const unsigned long long ah = MK_DESC(base + OFF_AH);
        const unsigned long long al = MK_DESC(base + OFF_AL);
        const unsigned long long bh = MK_DESC(base + OFF_WH);
        const unsigned long long bl = MK_DESC(base + OFF_WL);
#pragma unroll
        for (int ks = 0; ks < 16; ks++) {
            const int ao = 2 * (ks & 3) + 1024 * (ks >> 2);
            const int bo = 2 * (ks & 3) + 256 * (ks >> 2);
            mma_f16_ss(tmem, ah + ao, bh + bo, IDESC, ks ? 1u : 0u);
            mma_f16_ss(tmem, ah + ao, bl + bo, IDESC, 1u);
            mma_f16_ss(tmem, al + ao, bh + bo, IDESC, 1u);
        }
        TC_COMMIT(base + 8);
        // tid0 alone waits MMA completion; everyone else sleeps at the BAR.
        MBAR_WAITP(base + 8, 0);
    }
    __syncthreads();
    asm volatile("tcgen05.fence::after_thread_sync;" ::: "memory");

    // Read TMEM and publish partial. d0 stays live for the winner path.
    uint32_t d0[32];
    if (wid < 4) {
        LDTM_X32(d0, tmem);
        asm volatile("tcgen05.wait::ld.sync.aligned;" ::: "memory");
        float* pp = &gPart[kz][(size_t)(m0 + wid * 32 + lid) * ND + n0];
#pragma unroll
        for (int g = 0; g < 8; g++) {
            float4 r;
            r.x = __uint_as_float(d0[4 * g + 0]);
            r.y = __uint_as_float(d0[4 * g + 1]);
            r.z = __uint_as_float(d0[4 * g + 2]);
            r.w = __uint_as_float(d0[4 * g + 3]);
            *(float4*)(pp + 4 * g) = r;
        }
    }

    // Fence-promotion join (decoupled-lookback pattern): BAR makes the CTA's
    // STGs CTA-visible; tid0's gpu-scope fence promotes them (cumulativity),
    // the atomic publishes; on the winner the second fence is the acquire.
    __syncthreads();
    if (tid == 0) {
        asm volatile("fence.acq_rel.gpu;" ::: "memory");
        const int old = atomicAdd(&gCnt[tile], 1);
        asm volatile("fence.acq_rel.gpu;" ::: "memory");
        *(int*)(dbase + 64) = (old == 1);
    }
    __syncthreads();

    if (*(int*)(dbase + 64)) {
        // Winner: own partial is still in d0 registers; read only the peer.
        if (wid < 4) {
            const float* peer =
                &gPart[1 - kz][(size_t)(m0 + wid * 32 + lid) * ND + n0];
            float* yr = Y + (size_t)(m0 + wid * 32 + lid) * ND + n0;
            const float4* bias4 = (const float4*)(dbase + 128);
#pragma unroll
            for (int g = 0; g < 8; g++) {
                float4 pq = *(const float4*)(peer + 4 * g);
                float4 bb = bias4[g];
                float4 r;
                r.x = __uint_as_float(d0[4 * g + 0]) + pq.x + bb.x;
                r.y = __uint_as_float(d0[4 * g + 1]) + pq.y + bb.y;
                r.z = __uint_as_float(d0[4 * g + 2]) + pq.z + bb.z;
                r.w = __uint_as_float(d0[4 * g + 3]) + pq.w + bb.w;
                *(float4*)(yr + 4 * g) = r;
            }
        }
        if (tid == 0) gCnt[tile] = 0;  // reset for next graph replay
    }

    __syncthreads();
    if (wid == 0) {
        asm volatile("tcgen05.relinquish_alloc_permit.cta_group::1.sync.aligned;");
        asm volatile("tcgen05.dealloc.cta_group::1.sync.aligned.b32 %0, %1;"
                     :: "r"(tmem), "r"(64u));
    }
#else
    // ---- generic-target fallback (compiles everywhere; never runs) -------
    __shared__ int sflag;
    const int r = tid >> 2;               // 0..127
    const int g = tid & 3;                // 8 n cols each
    float acc[8];
#pragma unroll
    for (int j = 0; j < 8; j++) acc[j] = 0.f;
    for (int k = kz * KH; k < kz * KH + KH; k++) {
        const float a = X[(size_t)(m0 + r) * KD + k];
        const float* wr = W + (size_t)k * ND + n0 + 8 * g;
#pragma unroll
        for (int j = 0; j < 8; j++) acc[j] += a * wr[j];
    }
    {
        float* pp = &gPart[kz][(size_t)(m0 + r) * ND + n0 + 8 * g];
#pragma unroll
        for (int j = 0; j < 8; j++) pp[j] = acc[j];
    }
    __threadfence();
    __syncthreads();
    if (tid == 0) sflag = (atomicAdd(&gCnt[tile], 1) == 1);
    __syncthreads();
    if (sflag) {
        __threadfence();
#pragma unroll
        for (int j = 0; j < 2; j++) {
            const int u = j * 512 + tid;
            const int row = u >> 3, q = u & 7;
            const size_t idx = (size_t)(m0 + row) * ND + n0 + 4 * q;
            float4 p0 = *(const float4*)&gPart[0][idx];
            float4 p1 = *(const float4*)&gPart[1][idx];
            float4 bb = *(const float4*)(Bias + n0 + 4 * q);
            float4 rr;
            rr.x = p0.x + p1.x + bb.x;
            rr.y = p0.y + p1.y + bb.y;
            rr.z = p0.z + p1.z + bb.z;
            rr.w = p0.w + p1.w + bb.w;
            *(float4*)(Y + idx) = rr;
        }
        if (tid == 0) gCnt[tile] = 0;
    }
#endif
}

extern "C" void kernel_launch(void* const* d_in, const int* in_sizes, int n_in,
                              void* d_out, int out_size) {
    const float* x = (const float*)d_in[0];  // [512, 512]
    const float* w = (const float*)d_in[1];  // [512, 512]
    const float* b = (const float*)d_in[2];  // [512]
    float* y = (float*)d_out;                // [512, 512]

    static bool attr_done = false;
    if (!attr_done) {
        cudaFuncSetAttribute(fused_kernel,
                             cudaFuncAttributeMaxDynamicSharedMemorySize,
                             SMEM_DYN);
        attr_done = true;
    }

    dim3 grid(ND / 32, MD / 128, 2);  // (16, 4, 2) = 128 CTAs, one wave
    fused_kernel<<<grid, 512, SMEM_DYN>>>(x, w, b, y);
}